// round 13
// baseline (speedup 1.0000x reference)
#include <cuda_runtime.h>
#include <cstdint>

// VoxelHashTable: 2-level hash-grid trilinear interpolation — SPLIT PIPELINE.
// Inputs (metadata order):
//   d_in[0] query_pts (M,3) f32
//   d_in[1] feats0    (n0,32) f32
//   d_in[2] feats1    (n1,32) f32
//   d_in[3] h2v0      (2^20) i32
//   d_in[4] h2v1      (2^20) i32
// Output: (M, 64) f32  — [level0 32 | level1 32]
//
// The single-kernel forms plateau at ~80us because the
// hash-LDG -> shfl -> feature-LDG dependency chain caps L1 wavefront
// utilization at ~80%. Split into two latency-tolerant streams:
//   K1 (hash): one thread per (query, level, corner) — scattered 4B table
//       read, coalesced 4B scratch write. No consumers -> unbounded MLP.
//   K2 (gather): warp = 2 queries (R4 layout). Voxel indices arrive via ONE
//       coalesced 128B scratch read per warp (g_vidx[pair*32 + lane]), so the
//       8 feature-row loads per (query,level) are independent immediately.
// Scratch: 32MB __device__ global (allocation-free rule).

#define TSIZE_MASK ((1 << 20) - 1)

// PRIMES % 2^20 (exact):
#define PMX 455773
#define PMY 475301
#define PMZ 655287

#define MAX_Q 500000
// Layout: g_vidx[q*16 + level*8 + corner]  ==  g_vidx[pair*32 + lane] in K2.
__device__ int g_vidx[MAX_Q * 16];

// ---------------- K1: hash lookups ----------------
__global__ __launch_bounds__(256, 8) void hash_kernel(
    const float* __restrict__ q,
    const int* __restrict__ h0,
    const int* __restrict__ h1,
    int M)
{
    const int tid = blockIdx.x * blockDim.x + threadIdx.x;
    const int qi = tid >> 4;
    if (qi >= M) return;

    const int level  = (tid >> 3) & 1;
    const int corner = tid & 7;

    const float px = __ldg(q + qi * 3 + 0);
    const float py = __ldg(q + qi * 3 + 1);
    const float pz = __ldg(q + qi * 3 + 2);

    const float res = level ? 0.24f : 0.12f;   // 0.24f == float32(0.12*2.0)
    const float sx = __fdiv_rn(px, res);
    const float sy = __fdiv_rn(py, res);
    const float sz = __fdiv_rn(pz, res);

    const int cx = (int)floorf(sx) + ((corner >> 2) & 1);
    const int cy = (int)floorf(sy) + ((corner >> 1) & 1);
    const int cz = (int)floorf(sz) + (corner & 1);

    const unsigned hv =
        ((unsigned)(cx * PMX + cy * PMY + cz * PMZ)) & TSIZE_MASK;

    const int* __restrict__ hp = level ? h1 : h0;
    g_vidx[tid] = __ldg(hp + hv);
}

// ---------------- K2: trilinear gather ----------------
// Warp layout (1 warp = 2 queries):
//   half  = lane>>4, level = (lane>>3)&1, s = lane&7 (float4 chunk)
__global__ __launch_bounds__(256, 8) void gather_kernel(
    const float* __restrict__ q,
    const float* __restrict__ f0,
    const float* __restrict__ f1,
    float* __restrict__ out,
    int M)
{
    const int pair = (blockIdx.x * blockDim.x + threadIdx.x) >> 5;
    const int lane = threadIdx.x & 31;

    const int level = (lane >> 3) & 1;
    const int s     = lane & 7;

    int qidx = pair * 2 + (lane >> 4);
    const bool active = qidx < M;
    if (qidx >= M) qidx = M - 1;

    // Coalesced: 32 consecutive ints = this warp's 32 precomputed indices.
    // (Only meaningful when pair*32+lane < M*16; clamp pair for the tail.)
    int vpair = pair;
    if (vpair * 32 + 31 >= M * 16) vpair = (M * 16 - 32) / 32;
    const int vidx = __ldg(&g_vidx[vpair * 32 + lane]);

    const float qx = __ldg(q + qidx * 3 + 0);
    const float qy = __ldg(q + qidx * 3 + 1);
    const float qz = __ldg(q + qidx * 3 + 2);

    const float res = level ? 0.24f : 0.12f;
    const float sx = __fdiv_rn(qx, res);
    const float sy = __fdiv_rn(qy, res);
    const float sz = __fdiv_rn(qz, res);
    const float bx = floorf(sx), by = floorf(sy), bz = floorf(sz);
    const float fx = sx - bx, fy = sy - by, fz = sz - bz;

    const float gx = 1.0f - fx;
    const float gy = 1.0f - fy;
    const float gz = 1.0f - fz;
    const float* __restrict__ fp = (level ? f1 : f0) + s * 4;

    const int src_base = lane & 0x18;   // (half<<4) | (level<<3)

    float4 acc = make_float4(0.f, 0.f, 0.f, 0.f);

    #pragma unroll
    for (int t = 0; t < 8; ++t) {
        const int v = __shfl_sync(0xFFFFFFFFu, vidx, src_base + t);

        // ((wx*wy)*wz) multiply order matches reference prod(axis=2).
        const float w = ((t & 4) ? fx : gx) *
                        ((t & 2) ? fy : gy) *
                        ((t & 1) ? fz : gz);

        if (v >= 0) {
            const float4 f = __ldg((const float4*)(fp + (size_t)v * 32));
            acc.x = fmaf(f.x, w, acc.x);
            acc.y = fmaf(f.y, w, acc.y);
            acc.z = fmaf(f.z, w, acc.z);
            acc.w = fmaf(f.w, w, acc.w);
        }
    }

    if (active) {
        *(float4*)(out + (size_t)qidx * 64 + level * 32 + s * 4) = acc;
    }
}

extern "C" void kernel_launch(void* const* d_in, const int* in_sizes, int n_in,
                              void* d_out, int out_size)
{
    const float* q  = (const float*)d_in[0];
    const float* f0 = (const float*)d_in[1];
    const float* f1 = (const float*)d_in[2];
    const int*   h0 = (const int*)d_in[3];
    const int*   h1 = (const int*)d_in[4];
    float* out = (float*)d_out;

    const int M = in_sizes[0] / 3;

    // K1: one thread per (query, level, corner) = 16*M threads.
    {
        const long long total = (long long)M * 16;
        const int blocks = (int)((total + 255) / 256);
        hash_kernel<<<blocks, 256>>>(q, h0, h1, M);
    }

    // K2: one warp per query pair.
    {
        const int pairs = (M + 1) / 2;
        const int blocks = (pairs + 7) / 8;   // 8 warps per block
        gather_kernel<<<blocks, 256>>>(q, f0, f1, out, M);
    }
}

// round 14
// speedup vs baseline: 1.3216x; 1.3216x over previous
#include <cuda_runtime.h>
#include <cstdint>

// VoxelHashTable: 2-level hash-grid trilinear interpolation.
// Inputs (metadata order):
//   d_in[0] query_pts (M,3) f32
//   d_in[1] feats0    (n0,32) f32
//   d_in[2] feats1    (n1,32) f32
//   d_in[3] h2v0      (2^20) i32
//   d_in[4] h2v1      (2^20) i32
// Output: (M, 64) f32  — [level0 32 | level1 32]
//
// Warp layout (1 warp = 4 queries, two pairs A, B — the proven R7 shape):
//   half  = lane>>4, level = (lane>>3)&1, s = lane&7 (float4 chunk)
//
// KEY CHANGE vs R7: q/res replaced by q * (1/res). The f32 divide expands to
// MUFU.RCP + FFMA refinement; at 24M divides/launch the MUFU pipe (invisible
// in the ncu summary) was the ~80us plateau. Reciprocal-multiply differs from
// round-to-nearest divide by <=1-2 ulp; floor() can flip only when q/res is
// within an ulp of an integer, and the trilinear interpolant is CONTINUOUS
// across voxel-plane boundaries (the differing corners carry vanishing
// weight; both bases converge to the same shared-plane bilinear value, even
// with hash misses), so flips perturb the output by O(ulp) only.
//
// __launch_bounds__(256, 6): 40-reg budget ((256,7) truncates to 32 + spills).

#define TSIZE_MASK ((1 << 20) - 1)

// PRIMES % 2^20 (exact):
#define PMX 455773
#define PMY 475301
#define PMZ 655287

#define INV_RES0 (1.0f / 0.12f)
#define INV_RES1 (1.0f / 0.24f)   // 0.24f == float32(0.12*2.0)

__global__ __launch_bounds__(256, 6) void voxel_hash_kernel(
    const float* __restrict__ q,
    const float* __restrict__ f0,
    const float* __restrict__ f1,
    const int* __restrict__ h0,
    const int* __restrict__ h1,
    float* __restrict__ out,
    int M)
{
    const int wid  = (blockIdx.x * blockDim.x + threadIdx.x) >> 5;
    const int lane = threadIdx.x & 31;

    const int level = (lane >> 3) & 1;
    const int s     = lane & 7;
    const int half  = lane >> 4;

    const int base = wid * 4;
    int qA = base + half;
    int qB = base + 2 + half;
    const bool actA = qA < M;
    const bool actB = qB < M;
    if (qA >= M) qA = M - 1;
    if (qB >= M) qB = M - 1;

    const float inv_res = level ? INV_RES1 : INV_RES0;
    const int*   __restrict__ hp = level ? h1 : h0;
    const float* __restrict__ fp = (level ? f1 : f0) + s * 4;
    const int src_base = lane & 0x18;          // (half<<4) | (level<<3)
    const int oxb = (lane >> 2) & 1;
    const int oyb = (lane >> 1) & 1;
    const int ozb = lane & 1;

    // ---- Prologue: both pairs' query points + hash lookups in flight ----
    const float qAx = __ldg(q + qA * 3 + 0);
    const float qAy = __ldg(q + qA * 3 + 1);
    const float qAz = __ldg(q + qA * 3 + 2);
    const float qBx = __ldg(q + qB * 3 + 0);
    const float qBy = __ldg(q + qB * 3 + 1);
    const float qBz = __ldg(q + qB * 3 + 2);

    const float sxA = qAx * inv_res;
    const float syA = qAy * inv_res;
    const float szA = qAz * inv_res;
    const float bxA = floorf(sxA), byA = floorf(syA), bzA = floorf(szA);
    const float fxA = sxA - bxA, fyA = syA - byA, fzA = szA - bzA;

    int vidxA;
    {
        const unsigned hv = ((unsigned)(((int)bxA + oxb) * PMX +
                                        ((int)byA + oyb) * PMY +
                                        ((int)bzA + ozb) * PMZ)) & TSIZE_MASK;
        vidxA = __ldg(hp + hv);
    }

    const float sxB = qBx * inv_res;
    const float syB = qBy * inv_res;
    const float szB = qBz * inv_res;
    const float bxB = floorf(sxB), byB = floorf(syB), bzB = floorf(szB);
    const float fxB = sxB - bxB, fyB = syB - byB, fzB = szB - bzB;

    int vidxB;
    {
        const unsigned hv = ((unsigned)(((int)bxB + oxb) * PMX +
                                        ((int)byB + oyb) * PMY +
                                        ((int)bzB + ozb) * PMZ)) & TSIZE_MASK;
        vidxB = __ldg(hp + hv);
    }

    // ---- Gather A ----
    {
        const float gx = 1.0f - fxA, gy = 1.0f - fyA, gz = 1.0f - fzA;
        float4 acc = make_float4(0.f, 0.f, 0.f, 0.f);
        #pragma unroll
        for (int t = 0; t < 8; ++t) {
            const int v = __shfl_sync(0xFFFFFFFFu, vidxA, src_base + t);
            // ((wx*wy)*wz) multiply order matches reference prod(axis=2).
            const float w = ((t & 4) ? fxA : gx) *
                            ((t & 2) ? fyA : gy) *
                            ((t & 1) ? fzA : gz);
            if (v >= 0) {
                const float4 f = __ldg((const float4*)(fp + (size_t)v * 32));
                acc.x = fmaf(f.x, w, acc.x);
                acc.y = fmaf(f.y, w, acc.y);
                acc.z = fmaf(f.z, w, acc.z);
                acc.w = fmaf(f.w, w, acc.w);
            }
        }
        if (actA) {
            *(float4*)(out + (size_t)qA * 64 + level * 32 + s * 4) = acc;
        }
    }

    // ---- Gather B ----
    {
        const float gx = 1.0f - fxB, gy = 1.0f - fyB, gz = 1.0f - fzB;
        float4 acc = make_float4(0.f, 0.f, 0.f, 0.f);
        #pragma unroll
        for (int t = 0; t < 8; ++t) {
            const int v = __shfl_sync(0xFFFFFFFFu, vidxB, src_base + t);
            const float w = ((t & 4) ? fxB : gx) *
                            ((t & 2) ? fyB : gy) *
                            ((t & 1) ? fzB : gz);
            if (v >= 0) {
                const float4 f = __ldg((const float4*)(fp + (size_t)v * 32));
                acc.x = fmaf(f.x, w, acc.x);
                acc.y = fmaf(f.y, w, acc.y);
                acc.z = fmaf(f.z, w, acc.z);
                acc.w = fmaf(f.w, w, acc.w);
            }
        }
        if (actB) {
            *(float4*)(out + (size_t)qB * 64 + level * 32 + s * 4) = acc;
        }
    }
}

extern "C" void kernel_launch(void* const* d_in, const int* in_sizes, int n_in,
                              void* d_out, int out_size)
{
    const float* q  = (const float*)d_in[0];
    const float* f0 = (const float*)d_in[1];
    const float* f1 = (const float*)d_in[2];
    const int*   h0 = (const int*)d_in[3];
    const int*   h1 = (const int*)d_in[4];
    float* out = (float*)d_out;

    const int M = in_sizes[0] / 3;
    const int warps = (M + 3) / 4;          // 4 queries per warp

    const int warps_per_block = 8;
    const int blocks = (warps + warps_per_block - 1) / warps_per_block;
    voxel_hash_kernel<<<blocks, warps_per_block * 32>>>(q, f0, f1, h0, h1, out, M);
}